// round 14
// baseline (speedup 1.0000x reference)
#include <cuda_runtime.h>

#define NW      10000
#define MAXLEN  14
#define QCOUNT  32     // BSZ*SEQ
#define TPB     64
#define SORT_B  256
#define NSB     ((NW + SORT_B - 1) / SORT_B)

// Scratch (no allocation allowed)
__device__ int g_wlen_s[NW];
__device__ int g_orig_s[NW];
__device__ int g_qorder[QCOUNT];

// -------------------------------------------------------------------------
// Fused counting-sort, DESCENDING length (heavy-first). PACKING REMOVED —
// dl reads word chars directly from `words` by original index, so this
// kernel touches only wl (40KB, L2-hot) + 10K scatter stores.
// Block 0 emits g_qorder via parallel stable rank (descending swl).
// -------------------------------------------------------------------------
__global__ void __launch_bounds__(SORT_B)
fused_sort_kernel(const int* __restrict__ wl, const int* __restrict__ x) {
    __shared__ int h_all[MAXLEN + 2];
    __shared__ int h_bef[MAXLEN + 2];
    __shared__ int h_rank[MAXLEN + 2];
    __shared__ int base[MAXLEN + 2];

    const int t = threadIdx.x;
    const int blockStart = blockIdx.x * SORT_B;

    if (t <= MAXLEN + 1) { h_all[t] = 0; h_bef[t] = 0; h_rank[t] = 0; }
    __syncthreads();

    const uint4* wl4 = (const uint4*)wl;
    for (int v = t; v < NW / 4; v += SORT_B) {
        uint4 w4 = wl4[v];
        int idx = v * 4;
        atomicAdd(&h_all[w4.x], 1); if (idx + 0 < blockStart) atomicAdd(&h_bef[w4.x], 1);
        atomicAdd(&h_all[w4.y], 1); if (idx + 1 < blockStart) atomicAdd(&h_bef[w4.y], 1);
        atomicAdd(&h_all[w4.z], 1); if (idx + 2 < blockStart) atomicAdd(&h_bef[w4.z], 1);
        atomicAdd(&h_all[w4.w], 1); if (idx + 3 < blockStart) atomicAdd(&h_bef[w4.w], 1);
    }
    __syncthreads();

    if (t == 0) {
        int acc = 0;
        for (int l = MAXLEN; l >= 1; --l) { base[l] = acc; acc += h_all[l]; }  // descending
    }
    __syncthreads();

    const int w = blockStart + t;
    if (w < NW) {
        int len  = wl[w];
        int rank = atomicAdd(&h_rank[len], 1);
        int pos  = base[len] + h_bef[len] + rank;
        g_wlen_s[pos] = len;
        g_orig_s[pos] = w;
    }

    // Block 0: q-order by descending swl — parallel stable rank.
    if (blockIdx.x == 0) {
        __shared__ int s_swl[QCOUNT];
        if (t < QCOUNT) {
            int sw = 0, best = x[t * (MAXLEN + 1)];
            #pragma unroll
            for (int c = 1; c <= MAXLEN; ++c) {
                int v = x[t * (MAXLEN + 1) + c];
                if (v > best) { best = v; sw = c; }
            }
            s_swl[t] = sw;
        }
        __syncthreads();
        if (t < QCOUNT) {
            int mine = s_swl[t];
            int rank = 0;
            #pragma unroll
            for (int j = 0; j < QCOUNT; ++j) {
                int sj = s_swl[j];
                rank += (sj > mine) || (sj == mine && j < t);
            }
            g_qorder[rank] = t;
        }
    }
}

// -------------------------------------------------------------------------
// Main kernel: EXACT R13 DP structure (26.2us / 64 regs proven). One thread
// per (query, sorted word); word chars loaded directly from `words` by
// original index (7x int2, 56B rows are 8-aligned; L2-hot across q-blocks).
// q = g_qorder[blockIdx.y] (heavy-first).
// -------------------------------------------------------------------------
__global__ void __launch_bounds__(TPB)
dl_kernel(const int* __restrict__ x, const int* __restrict__ words,
          float* __restrict__ out) {
    __shared__ unsigned char d_s[14 * 16 * TPB];   // 224 B per thread
    __shared__ int s_x[MAXLEN + 1];

    const int tid  = threadIdx.x;
    const int q    = g_qorder[blockIdx.y];
    const int slot = blockIdx.x * TPB + tid;

    if (tid < MAXLEN + 1) s_x[tid] = x[q * (MAXLEN + 1) + tid];
    __syncthreads();

    // swl = first-argmax over the 15 chars (jnp.argmax semantics)
    int swl = 0, best = s_x[0];
    #pragma unroll
    for (int t = 1; t <= MAXLEN; ++t) {
        int v = s_x[t];
        if (v > best) { best = v; swl = t; }
    }

    int wlen = 0, orig = 0;
    if (slot < NW) {
        wlen = g_wlen_s[slot];
        orig = g_orig_s[slot];
    }

    // Word chars straight from gmem (int2-vectorized; values are small ints)
    int wc[MAXLEN];
    {
        const int2* wrow = (const int2*)(words + orig * MAXLEN);
        #pragma unroll
        for (int c = 0; c < MAXLEN / 2; ++c) {
            int2 v = wrow[c];
            wc[2 * c]     = v.x;
            wc[2 * c + 1] = v.y;
        }
    }
    int kreg[MAXLEN];
    #pragma unroll
    for (int c = 0; c < MAXLEN; ++c) kreg[c] = 0;

    const int maxd = swl + wlen;
    unsigned char* bp = d_s + tid;

    // Init gather-reachable boundary cells (rows 0..swl-1, cols 0..wlen-1):
    //   d[0][l] = maxd ; d[1][0] = maxd ; d[1][l>=1] = l-1
    //   d[k][0] = maxd, d[k][1] = k-1   for k = 2..swl-1
    for (int l = 0; l < wlen; ++l) {
        bp[(0 * 16 + l) * TPB] = (unsigned char)maxd;
        bp[(1 * 16 + l) * TPB] = (unsigned char)(l == 0 ? maxd : l - 1);
    }
    for (int k = 2; k < swl; ++k) {
        bp[(k * 16 + 0) * TPB] = (unsigned char)maxd;
        bp[(k * 16 + 1) * TPB] = (unsigned char)(k - 1);
    }

    // prev[j] = d[i][j]; row 1: d[1][j] = j-1
    int prev[16];
    #pragma unroll
    for (int j = 1; j <= 15; ++j) prev[j] = j - 1;

    int res = wlen;                        // swl == 0: d[1][wlen+1] = wlen
    const int rlimit = swl - 2;            // last row whose store matters
    const int climit = wlen - 2;           // last col whose store matters
    for (int i = 1; i <= swl; ++i) {       // uniform per block
        const int xc  = s_x[i - 1];
        const int im1 = i - 1;
        int db   = 0;
        int left = i;                      // d[i+1][1] = i
        unsigned char* rowp = bp + ((i + 1) * 16) * TPB;
        const bool rkeep = (i <= rlimit);
        #pragma unroll
        for (int j = 1; j <= 15; ++j) {
            if (j > wlen || j == 15) { prev[j] = left; break; }   // d[i+1][j]
            const bool p  = (xc == wc[j - 1]);
            const int up   = prev[j + 1];
            const int diag = prev[j];
            const int k = kreg[j - 1];
            const int l = db;
            const int dtr   = (int)bp[(k * 16 + l) * TPB];        // LDS.U8
            const int trans = dtr + (im1 + j - k - l);
            int m = min(up, left) + 1;
            m = min(m, diag + (p ? 0 : 1));
            m = min(m, trans);
            if (p) { db = j; kreg[j - 1] = i; }
            if (rkeep && j <= climit)
                rowp[(j + 1) * TPB] = (unsigned char)m;           // d[i+1][j+1]
            prev[j] = left;
            left = m;
        }
        res = left;                        // d[i+1][wlen+1]
    }

    if (slot < NW) out[q * NW + orig] = (float)res;
}

// -------------------------------------------------------------------------
extern "C" void kernel_launch(void* const* d_in, const int* in_sizes, int n_in,
                              void* d_out, int out_size) {
    const int* x     = (const int*)d_in[0];   // (2,16,15) int32
    const int* words = (const int*)d_in[1];   // (10000,14) int32
    const int* wl    = (const int*)d_in[2];   // (10000,) int32
    float* out = (float*)d_out;               // (2,16,10000) float32

    fused_sort_kernel<<<NSB, SORT_B>>>(wl, x);
    dim3 grid((NW + TPB - 1) / TPB, QCOUNT);
    dl_kernel<<<grid, TPB>>>(x, words, out);
}

// round 15
// speedup vs baseline: 1.0624x; 1.0624x over previous
#include <cuda_runtime.h>

#define NW      10000
#define MAXLEN  14
#define QCOUNT  32     // BSZ*SEQ
#define TPB     64
#define SORT_B  256
#define NSB     ((NW + SORT_B - 1) / SORT_B)

// Scratch (no allocation allowed)
__device__ int   g_wlen_s[NW];
__device__ int   g_orig_s[NW];
__device__ uint4 g_packed[NW];
__device__ int   g_qorder[QCOUNT];

// -------------------------------------------------------------------------
// Fused counting-sort, DESCENDING length (heavy-first), WITH packing
// (R13-proven: coalesced pack here beats scattered reads in dl).
// Block 0 emits g_qorder via parallel stable rank (descending swl).
// -------------------------------------------------------------------------
__global__ void __launch_bounds__(SORT_B)
fused_sort_kernel(const int* __restrict__ words, const int* __restrict__ wl,
                  const int* __restrict__ x) {
    __shared__ int h_all[MAXLEN + 2];
    __shared__ int h_bef[MAXLEN + 2];
    __shared__ int h_rank[MAXLEN + 2];
    __shared__ int base[MAXLEN + 2];

    const int t = threadIdx.x;
    const int blockStart = blockIdx.x * SORT_B;

    if (t <= MAXLEN + 1) { h_all[t] = 0; h_bef[t] = 0; h_rank[t] = 0; }
    __syncthreads();

    const uint4* wl4 = (const uint4*)wl;
    for (int v = t; v < NW / 4; v += SORT_B) {
        uint4 w4 = wl4[v];
        int idx = v * 4;
        atomicAdd(&h_all[w4.x], 1); if (idx + 0 < blockStart) atomicAdd(&h_bef[w4.x], 1);
        atomicAdd(&h_all[w4.y], 1); if (idx + 1 < blockStart) atomicAdd(&h_bef[w4.y], 1);
        atomicAdd(&h_all[w4.z], 1); if (idx + 2 < blockStart) atomicAdd(&h_bef[w4.z], 1);
        atomicAdd(&h_all[w4.w], 1); if (idx + 3 < blockStart) atomicAdd(&h_bef[w4.w], 1);
    }
    __syncthreads();

    if (t == 0) {
        int acc = 0;
        for (int l = MAXLEN; l >= 1; --l) { base[l] = acc; acc += h_all[l]; }  // descending
    }
    __syncthreads();

    const int w = blockStart + t;
    if (w < NW) {
        int len  = wl[w];
        int rank = atomicAdd(&h_rank[len], 1);
        int pos  = base[len] + h_bef[len] + rank;
        g_wlen_s[pos] = len;
        g_orig_s[pos] = w;
        unsigned int p[4] = {0u, 0u, 0u, 0u};
        #pragma unroll
        for (int c = 0; c < MAXLEN; ++c) {
            unsigned int ch = (unsigned int)words[w * MAXLEN + c] & 0xFFu;
            p[c >> 2] |= ch << ((c & 3) * 8);
        }
        g_packed[pos] = make_uint4(p[0], p[1], p[2], p[3]);
    }

    // Block 0: q-order by descending swl — parallel stable rank.
    if (blockIdx.x == 0) {
        __shared__ int s_swl[QCOUNT];
        if (t < QCOUNT) {
            int sw = 0, best = x[t * (MAXLEN + 1)];
            #pragma unroll
            for (int c = 1; c <= MAXLEN; ++c) {
                int v = x[t * (MAXLEN + 1) + c];
                if (v > best) { best = v; sw = c; }
            }
            s_swl[t] = sw;
        }
        __syncthreads();
        if (t < QCOUNT) {
            int mine = s_swl[t];
            int rank = 0;
            #pragma unroll
            for (int j = 0; j < QCOUNT; ++j) {
                int sj = s_swl[j];
                rank += (sj > mine) || (sj == mine && j < t);
            }
            g_qorder[rank] = t;
        }
    }
}

// -------------------------------------------------------------------------
// Main kernel: R13 DP structure (26.2us / 64 regs proven) with the smem
// matrix shrunk 16 -> 14 columns (all touched indices <= 13: stores at
// col j+1 <= wlen-1, gathers at l <= wlen-1). 12.25 KB/block -> 18
// blocks/SM = 36 warps (was 15/30). q = g_qorder[blockIdx.y] (heavy-first).
// -------------------------------------------------------------------------
__global__ void __launch_bounds__(TPB)
dl_kernel(const int* __restrict__ x, float* __restrict__ out) {
    __shared__ unsigned char d_s[14 * 14 * TPB];   // 196 B per thread
    __shared__ int s_x[MAXLEN + 1];

    const int tid  = threadIdx.x;
    const int q    = g_qorder[blockIdx.y];
    const int slot = blockIdx.x * TPB + tid;

    if (tid < MAXLEN + 1) s_x[tid] = x[q * (MAXLEN + 1) + tid];
    __syncthreads();

    // swl = first-argmax over the 15 chars (jnp.argmax semantics)
    int swl = 0, best = s_x[0];
    #pragma unroll
    for (int t = 1; t <= MAXLEN; ++t) {
        int v = s_x[t];
        if (v > best) { best = v; swl = t; }
    }

    int wlen = 0, orig = 0;
    unsigned int pw0 = 0, pw1 = 0, pw2 = 0, pw3 = 0;
    if (slot < NW) {
        wlen = g_wlen_s[slot];
        orig = g_orig_s[slot];
        uint4 p = g_packed[slot];
        pw0 = p.x; pw1 = p.y; pw2 = p.z; pw3 = p.w;
    }

    int wc[MAXLEN];
    #pragma unroll
    for (int c = 0; c < MAXLEN; ++c) {
        unsigned int r = (c < 4) ? pw0 : (c < 8) ? pw1 : (c < 12) ? pw2 : pw3;
        wc[c] = (int)((r >> ((c & 3) * 8)) & 0xFFu);
    }
    int kreg[MAXLEN];
    #pragma unroll
    for (int c = 0; c < MAXLEN; ++c) kreg[c] = 0;

    const int maxd = swl + wlen;
    unsigned char* bp = d_s + tid;

    // Init gather-reachable boundary cells (rows 0..swl-1, cols 0..wlen-1):
    //   d[0][l] = maxd ; d[1][0] = maxd ; d[1][l>=1] = l-1
    //   d[k][0] = maxd, d[k][1] = k-1   for k = 2..swl-1
    for (int l = 0; l < wlen; ++l) {
        bp[(0 * 14 + l) * TPB] = (unsigned char)maxd;
        bp[(1 * 14 + l) * TPB] = (unsigned char)(l == 0 ? maxd : l - 1);
    }
    for (int k = 2; k < swl; ++k) {
        bp[(k * 14 + 0) * TPB] = (unsigned char)maxd;
        bp[(k * 14 + 1) * TPB] = (unsigned char)(k - 1);
    }

    // prev[j] = d[i][j]; row 1: d[1][j] = j-1
    int prev[16];
    #pragma unroll
    for (int j = 1; j <= 15; ++j) prev[j] = j - 1;

    int res = wlen;                        // swl == 0: d[1][wlen+1] = wlen
    const int rlimit = swl - 2;            // last row whose store matters
    const int climit = wlen - 2;           // last col whose store matters
    for (int i = 1; i <= swl; ++i) {       // uniform per block
        const int xc  = s_x[i - 1];
        const int im1 = i - 1;
        int db   = 0;
        int left = i;                      // d[i+1][1] = i
        unsigned char* rowp = bp + ((i + 1) * 14) * TPB;
        const bool rkeep = (i <= rlimit);
        #pragma unroll
        for (int j = 1; j <= 15; ++j) {
            if (j > wlen || j == 15) { prev[j] = left; break; }   // d[i+1][j]
            const bool p  = (xc == wc[j - 1]);
            const int up   = prev[j + 1];
            const int diag = prev[j];
            const int k = kreg[j - 1];
            const int l = db;
            const int dtr   = (int)bp[(k * 14 + l) * TPB];        // LDS.U8
            const int trans = dtr + (im1 + j - k - l);
            int m = min(up, left) + 1;
            m = min(m, diag + (p ? 0 : 1));
            m = min(m, trans);
            if (p) { db = j; kreg[j - 1] = i; }
            if (rkeep && j <= climit)
                rowp[(j + 1) * TPB] = (unsigned char)m;           // d[i+1][j+1]
            prev[j] = left;
            left = m;
        }
        res = left;                        // d[i+1][wlen+1]
    }

    if (slot < NW) out[q * NW + orig] = (float)res;
}

// -------------------------------------------------------------------------
extern "C" void kernel_launch(void* const* d_in, const int* in_sizes, int n_in,
                              void* d_out, int out_size) {
    const int* x     = (const int*)d_in[0];   // (2,16,15) int32
    const int* words = (const int*)d_in[1];   // (10000,14) int32
    const int* wl    = (const int*)d_in[2];   // (10000,) int32
    float* out = (float*)d_out;               // (2,16,10000) float32

    fused_sort_kernel<<<NSB, SORT_B>>>(words, wl, x);
    dim3 grid((NW + TPB - 1) / TPB, QCOUNT);
    dl_kernel<<<grid, TPB>>>(x, out);
}